// round 9
// baseline (speedup 1.0000x reference)
#include <cuda_runtime.h>
#include <cstdint>

// VarConvND via tcgen05 TF32 per-location GEMM (sm_103a), SIMT fallback body
// for the plain compute_103 PTX pass (never selected at runtime on GB300).
//
//   out[b, co, s] = sum_k (unfold(X)[b, k, s] + bias[s]) * weight[s, k, co]
//
// Pass 1: X (B,C,H,W) -> Xt (H,W,C,B).
// Pass 2: one block per s. M=64(pad 128) x N=64 x K=1152, tcgen05 tf32.
//         3-stage A/B smem ring with full/empty mbarriers; NO __syncthreads
//         in the mainloop (producers free-run up to 3 chunks ahead).
// Pass 3: transpose scratch (s, f) -> out (f, s).

#if defined(__CUDA_ARCH_FEAT_SM103_ALL) || defined(__CUDA_ARCH_FEAT_SM100_ALL)
#define HAS_TCGEN05 1
#else
#define HAS_TCGEN05 0
#endif

__device__ float g_Xt[32 * 32 * 128 * 64];      // 33.5 MB
__device__ float g_scratch[1024 * 64 * 64];     // 16.8 MB

// smem layout (byte offsets from 1024-aligned base):
//   A stages   [0, 24576)        3 x 8KB
//   B stages   [24576, 49152)    3 x 8KB
//   koff       [49152, 53760)    1152 x int
//   full mbar  [53760, 53784)    3 x u64  (count 256)
//   empty mbar [53784, 53808)    3 x u64  (count 1, armed by commit)
//   done mbar  [53808, 53816)    u64
//   tmem ptr   [53816, 53820)
#define SM_B     24576
#define SM_KOFF  49152
#define SM_FULL  53760
#define SM_EMPTY 53784
#define SM_DONE  53808
#define SM_TPTR  53816
#define DYN_BYTES (53824 + 1024)

// ---------------------------------------------------------------------------
// helpers
// ---------------------------------------------------------------------------
__device__ __forceinline__ uint32_t smem_u32(const void* p) {
    uint32_t a;
    asm("{ .reg .u64 t; cvta.to.shared.u64 t, %1; cvt.u32.u64 %0, t; }" : "=r"(a) : "l"(p));
    return a;
}
__device__ __forceinline__ uint32_t f2tf32(float f) {
    uint32_t r;
    asm("cvt.rna.tf32.f32 %0, %1;" : "=r"(r) : "f"(f));
    return r;
}
#define SWZ(o) ((o) ^ (((o) >> 3) & 0x70))

#if HAS_TCGEN05
__device__ __forceinline__ uint32_t elect_one() {
    uint32_t p;
    asm volatile("{ .reg .pred p; elect.sync _|p, 0xFFFFFFFF; selp.b32 %0,1,0,p; }" : "=r"(p));
    return p;
}

// K-major SW128: LBO=1, SBO=64 (proven rounds 4-6)
static constexpr uint64_t DESC_BASE =
    (uint64_t(2) << 61) | (uint64_t(1) << 46) | (uint64_t(64) << 32) | (uint64_t(1) << 16);
__device__ __forceinline__ uint64_t make_desc(uint32_t addr) {
    return DESC_BASE | ((uint64_t)(addr >> 4) & 0x3FFF);
}

// idesc kind::tf32: dtype=F32(1)<<4, atype=TF32(2)<<7, btype=TF32(2)<<10,
// N=64 -> 8<<17, M=128 -> 8<<24   (proven rounds 4-6)
#define IDESC_TF32 0x8100910u

__device__ __forceinline__ void mma_tf32(uint32_t d, uint64_t ad, uint64_t bd, uint32_t en) {
    asm volatile(
        "{\n\t.reg .pred p;\n\tsetp.ne.u32 p, %4, 0;\n\t"
        "tcgen05.mma.cta_group::1.kind::tf32 [%0], %1, %2, %3, {%5,%5,%5,%5}, p;\n\t}"
        :: "r"(d), "l"(ad), "l"(bd), "r"(IDESC_TF32), "r"(en), "r"(0u) : "memory");
}

#define MBARRIER_INIT(a, c) \
    asm volatile("mbarrier.init.shared.b64 [%0], %1;" :: "r"(a), "r"(c) : "memory")
#define MBARRIER_ARRIVE(a) \
    asm volatile("mbarrier.arrive.shared.b64 _, [%0];" :: "r"(a) : "memory")

#define MBAR_WAIT(addr, ph) do { \
    uint32_t _a = (addr), _p = (ph) & 1, _d; \
    asm volatile("{\n\t.reg .pred p;\n\tmbarrier.try_wait.parity.acquire.cta.shared::cta.b64 p, [%1], %2;\n\tselp.b32 %0,1,0,p;\n\t}" \
        : "=r"(_d) : "r"(_a), "r"(_p) : "memory"); \
    while (!_d) { \
        asm volatile("{\n\t.reg .pred p;\n\tmbarrier.try_wait.parity.acquire.cta.shared::cta.b64 p, [%1], %2, 0x989680;\n\tselp.b32 %0,1,0,p;\n\t}" \
            : "=r"(_d) : "r"(_a), "r"(_p) : "memory"); \
    } \
} while (0)

#define TCG_COMMIT(mb) \
    asm volatile("tcgen05.commit.cta_group::1.mbarrier::arrive::one.shared::cluster.b64 [%0];" :: "r"(mb) : "memory")
#define TCG_ALLOC(sa, n) \
    asm volatile("tcgen05.alloc.cta_group::1.sync.aligned.shared::cta.b32 [%0], %1;" :: "r"(sa), "r"(n) : "memory")
#define TCG_DEALLOC(t, n) \
    asm volatile("tcgen05.dealloc.cta_group::1.sync.aligned.b32 %0, %1;" :: "r"(t), "r"(n))
#define TCG_RELINQ() \
    asm volatile("tcgen05.relinquish_alloc_permit.cta_group::1.sync.aligned;")
#define TCG_WAIT_LD() asm volatile("tcgen05.wait::ld.sync.aligned;" ::: "memory")
#define TCG_FENCE_AFTER() asm volatile("tcgen05.fence::after_thread_sync;" ::: "memory")

#define TCG_LD_X32(r, ta) \
    asm volatile("tcgen05.ld.sync.aligned.32x32b.x32.b32 " \
        "{%0,%1,%2,%3,%4,%5,%6,%7,%8,%9,%10,%11,%12,%13,%14,%15," \
        "%16,%17,%18,%19,%20,%21,%22,%23,%24,%25,%26,%27,%28,%29,%30,%31}, [%32];" \
        : "=r"((r)[0]), "=r"((r)[1]), "=r"((r)[2]), "=r"((r)[3]), \
          "=r"((r)[4]), "=r"((r)[5]), "=r"((r)[6]), "=r"((r)[7]), \
          "=r"((r)[8]), "=r"((r)[9]), "=r"((r)[10]), "=r"((r)[11]), \
          "=r"((r)[12]), "=r"((r)[13]), "=r"((r)[14]), "=r"((r)[15]), \
          "=r"((r)[16]), "=r"((r)[17]), "=r"((r)[18]), "=r"((r)[19]), \
          "=r"((r)[20]), "=r"((r)[21]), "=r"((r)[22]), "=r"((r)[23]), \
          "=r"((r)[24]), "=r"((r)[25]), "=r"((r)[26]), "=r"((r)[27]), \
          "=r"((r)[28]), "=r"((r)[29]), "=r"((r)[30]), "=r"((r)[31]) \
        : "r"(ta))
#endif  // HAS_TCGEN05

// ---------------------------------------------------------------------------
// Pass 1: X (B=64, C=128, H=32, W=32) -> Xt (H, W, C, B)
// ---------------------------------------------------------------------------
__global__ void __launch_bounds__(256) transpose_kernel(const float* __restrict__ X) {
    __shared__ float sm[64][33];
    const int bx = blockIdx.x;
    const int c  = bx >> 5;
    const int yy = bx & 31;
    const int t  = threadIdx.x;
    #pragma unroll
    for (int p = 0; p < 8; p++) {
        const int b = p * 8 + (t >> 5);
        const int x = t & 31;
        sm[b][x] = X[(((b * 128 + c) * 32 + yy) << 5) + x];
    }
    __syncthreads();
    #pragma unroll
    for (int q = 0; q < 8; q++) {
        const int x = q * 4 + (t >> 6);
        const int b = t & 63;
        g_Xt[((((yy << 5) + x) * 128 + c) << 6) + b] = sm[b][x];
    }
}

// ---------------------------------------------------------------------------
// Pass 2: per-location GEMM, warp-desynchronized 3-stage pipeline
// ---------------------------------------------------------------------------
__global__ void __launch_bounds__(256) varconv_kernel(
    const float* __restrict__ W, const float* __restrict__ bias)
{
    extern __shared__ __align__(16) char dyn[];
    const uint32_t rawb = smem_u32(dyn);
    const uint32_t smb  = (rawb + 1023u) & ~1023u;
    char* smc = dyn + (smb - rawb);

    const int s = blockIdx.x;
    const int y = s >> 5, x0 = s & 31;
    const int tid = threadIdx.x;
    const float bs = bias[s];

#if HAS_TCGEN05
    const int wid = tid >> 5, lid = tid & 31;
    const int bq = tid & 63;        // batch row (A) / C_out row (B)
    const int kg = tid >> 6;        // k-subgroup 0..3 (8 k each)
    int* koff = (int*)(smc + SM_KOFF);

    if (wid == 0) { TCG_ALLOC(smb + SM_TPTR, 64); TCG_RELINQ(); }
    if (tid == 0) {
        #pragma unroll
        for (int st = 0; st < 3; st++) {
            MBARRIER_INIT(smb + SM_FULL  + st * 8, 256);
            MBARRIER_INIT(smb + SM_EMPTY + st * 8, 1);
        }
        MBARRIER_INIT(smb + SM_DONE, 1);
    }

    // --- per-block gather-offset table
    for (int k = tid; k < 1152; k += 256) {
        const int c  = k / 9;
        const int t9 = k - c * 9;
        const int ry = t9 / 3;
        const int rx = t9 - ry * 3;
        const int yy = y + ry - 1;
        const int xc = x0 + rx - 1;
        koff[k] = (((unsigned)yy < 32u) && ((unsigned)xc < 32u))
                      ? ((((yy << 5) + xc) * 128 + c) << 6) : -1;
    }
    __syncthreads();   // mbar init + koff visible; the ONLY block barrier pre-epilogue
    uint32_t tmem;
    asm("ld.shared.b32 %0, [%1];" : "=r"(tmem) : "r"(smb + SM_TPTR));

    const float* Wp = W + (size_t)s * 73728 + bq;   // + co
    uint32_t av[8], bv[8];
    auto loadAB = [&](int ci) {
        const int kb = ci * 32 + kg * 8;
        const float* wq = Wp + (size_t)kb * 64;
        #pragma unroll
        for (int u = 0; u < 8; u++) {
            const int off = koff[kb + u];
            float va = 0.0f;
            if (off >= 0) va = g_Xt[off + bq];
            av[u] = f2tf32(va + bs);
            bv[u] = f2tf32(__ldg(wq + u * 64));
        }
    };
    loadAB(0);

    const uint32_t aoff = (uint32_t)bq * 128 + (uint32_t)kg * 32;
    const uint32_t sw0 = SWZ(aoff), sw1 = SWZ(aoff + 16);

    int st = 0, pe = 1, pf = 0;
    for (int i = 0; i < 36; i++) {
        // producer: wait stage free (commit of MMA 3 chunks back)
        MBAR_WAIT(smb + SM_EMPTY + st * 8, pe);
        const uint32_t abase = st * 8192;
        *(uint4*)(smc + abase + sw0)        = make_uint4(av[0], av[1], av[2], av[3]);
        *(uint4*)(smc + abase + sw1)        = make_uint4(av[4], av[5], av[6], av[7]);
        *(uint4*)(smc + SM_B + abase + sw0) = make_uint4(bv[0], bv[1], bv[2], bv[3]);
        *(uint4*)(smc + SM_B + abase + sw1) = make_uint4(bv[4], bv[5], bv[6], bv[7]);
        if (i + 1 < 36) loadAB(i + 1);
        asm volatile("fence.proxy.async.shared::cta;" ::: "memory");
        MBARRIER_ARRIVE(smb + SM_FULL + st * 8);

        // consumer: elected lane issues the MMA chain for this chunk
        if (wid == 0 && elect_one()) {
            MBAR_WAIT(smb + SM_FULL + st * 8, pf);
            const uint64_t ad = make_desc(smb + abase);
            const uint64_t bd = make_desc(smb + SM_B + abase);
            mma_tf32(tmem, ad,     bd,     i > 0 ? 1u : 0u);
            mma_tf32(tmem, ad + 2, bd + 2, 1u);
            mma_tf32(tmem, ad + 4, bd + 4, 1u);
            mma_tf32(tmem, ad + 6, bd + 6, 1u);
            TCG_COMMIT(smb + SM_EMPTY + st * 8);
        }
        if (++st == 3) { st = 0; pe ^= 1; pf ^= 1; }
    }

    // all MMAs done -> done barrier (commit tracks all prior MMAs)
    if (wid == 0 && elect_one()) TCG_COMMIT(smb + SM_DONE);
    MBAR_WAIT(smb + SM_DONE, 0);
    TCG_FENCE_AFTER();

    if (wid < 2) {
        const int b = wid * 32 + lid;
        float* dst = g_scratch + ((size_t)s * 64 + b) * 64;
        uint32_t dr[32];
        TCG_LD_X32(dr, tmem);
        TCG_WAIT_LD();
        #pragma unroll
        for (int j = 0; j < 8; j++)
            ((uint4*)dst)[j] = make_uint4(dr[4 * j], dr[4 * j + 1], dr[4 * j + 2], dr[4 * j + 3]);
        TCG_LD_X32(dr, tmem + 32);
        TCG_WAIT_LD();
        #pragma unroll
        for (int j = 0; j < 8; j++)
            ((uint4*)(dst + 32))[j] = make_uint4(dr[4 * j], dr[4 * j + 1], dr[4 * j + 2], dr[4 * j + 3]);
    }
    __syncthreads();
    if (wid == 0) TCG_DEALLOC(tmem, 64);

#else  // ------- SIMT fallback (plain compute_103 pass; not selected on GB300)
    float (*As)[68] = (float(*)[68])smc;
    float (*Bs)[64] = (float(*)[64])(smc + 32 * 68 * 4);
    const int tx = tid & 15;
    const int ty = tid >> 4;
    const float* Wp = W + (size_t)s * 73728;

    float acc[4][4];
    #pragma unroll
    for (int i = 0; i < 4; i++)
        #pragma unroll
        for (int j = 0; j < 4; j++) acc[i][j] = 0.0f;

    for (int k0 = 0; k0 < 1152; k0 += 32) {
        {
            const float4* src = (const float4*)(Wp + k0 * 64);
            float4* dstB = (float4*)(&Bs[0][0]);
            dstB[tid]       = src[tid];
            dstB[tid + 256] = src[tid + 256];
        }
        #pragma unroll
        for (int i = 0; i < 2; i++) {
            const int kk = i * 16 + (tid >> 4);
            const int k  = k0 + kk;
            const int c   = k / 9;
            const int tap = k - c * 9;
            const int r   = tap / 3;
            const int cc  = tap - r * 3;
            const int yy = y + r - 1;
            const int xx = x0 + cc - 1;
            const int b4 = (tid & 15) << 2;
            float4 v = make_float4(0.f, 0.f, 0.f, 0.f);
            if (((unsigned)yy < 32u) && ((unsigned)xx < 32u))
                v = *(const float4*)(g_Xt + ((((yy << 5) + xx) * 128 + c) << 6) + b4);
            v.x += bs; v.y += bs; v.z += bs; v.w += bs;
            *(float4*)&As[kk][b4] = v;
        }
        __syncthreads();
        #pragma unroll
        for (int kk = 0; kk < 32; kk++) {
            const float4 a = *(const float4*)&As[kk][ty << 2];
            const float4 b = *(const float4*)&Bs[kk][tx << 2];
            acc[0][0] += a.x * b.x; acc[0][1] += a.x * b.y; acc[0][2] += a.x * b.z; acc[0][3] += a.x * b.w;
            acc[1][0] += a.y * b.x; acc[1][1] += a.y * b.y; acc[1][2] += a.y * b.z; acc[1][3] += a.y * b.w;
            acc[2][0] += a.z * b.x; acc[2][1] += a.z * b.y; acc[2][2] += a.z * b.z; acc[2][3] += a.z * b.w;
            acc[3][0] += a.w * b.x; acc[3][1] += a.w * b.y; acc[3][2] += a.w * b.z; acc[3][3] += a.w * b.w;
        }
        __syncthreads();
    }
    #pragma unroll
    for (int i = 0; i < 4; i++) {
        const int b = (ty << 2) + i;
        #pragma unroll
        for (int j = 0; j < 4; j++) {
            const int co = (tx << 2) + j;
            g_scratch[((size_t)s * 64 + b) * 64 + co] = acc[i][j];
        }
    }
#endif
}

// ---------------------------------------------------------------------------
// Pass 3: scratch (s, f) -> out (f, s), f = b*64 + co
// ---------------------------------------------------------------------------
__global__ void __launch_bounds__(256) out_transpose(float* __restrict__ out) {
    __shared__ float tile[32][33];
    const int f0 = blockIdx.x * 32;
    const int s0 = blockIdx.y * 32;
    const int tc = threadIdx.x & 31;
    const int tr = threadIdx.x >> 5;
    #pragma unroll
    for (int r = 0; r < 4; r++) {
        const int sl = tr * 4 + r;
        tile[sl][tc] = g_scratch[(size_t)(s0 + sl) * 4096 + f0 + tc];
    }
    __syncthreads();
    #pragma unroll
    for (int r = 0; r < 4; r++) {
        const int fl = tr * 4 + r;
        out[(size_t)(f0 + fl) * 1024 + s0 + tc] = tile[tc][fl];
    }
}

extern "C" void kernel_launch(void* const* d_in, const int* in_sizes, int n_in,
                              void* d_out, int out_size) {
    const float* X    = (const float*)d_in[0];
    const float* W    = (const float*)d_in[1];
    const float* bias = (const float*)d_in[2];
    float* out = (float*)d_out;

    cudaFuncSetAttribute(varconv_kernel,
                         cudaFuncAttributeMaxDynamicSharedMemorySize, DYN_BYTES);

    transpose_kernel<<<128 * 32, 256>>>(X);
    varconv_kernel<<<1024, 256, DYN_BYTES>>>(W, bias);
    out_transpose<<<dim3(128, 32), 256>>>(out);
}

// round 11
// speedup vs baseline: 1.1974x; 1.1974x over previous
#include <cuda_runtime.h>
#include <cstdint>

// VarConvND via tcgen05 TF32 per-location GEMM (sm_103a), SIMT fallback body
// for the plain compute_103 PTX pass (never selected at runtime on GB300).
//
//   out[b, co, s] = sum_k (unfold(X)[b, k, s] + bias[s]) * weight[s, k, co]
//
// K-order is permuted to tap-major (k' = tap*128 + c): each K32 chunk is one
// (tap, c-quarter) pair, so the A tile is a CONTIGUOUS 8KB block of Xt.
//
// Pass 1: X (B,C,H,W) -> Xt (H,W,B,C)  (c contiguous -> float4 A loads).
// Pass 2: one block per s. M=64(pad 128) x N=64 x K=1152, tcgen05 tf32,
//         2-stage smem pipeline (round-5 proven structure).
// Pass 3: transpose scratch (s, f) -> out (f, s).

#if defined(__CUDA_ARCH_FEAT_SM103_ALL) || defined(__CUDA_ARCH_FEAT_SM100_ALL)
#define HAS_TCGEN05 1
#else
#define HAS_TCGEN05 0
#endif

__device__ float g_Xt[32 * 32 * 64 * 128];      // (y, x, b, c) 33.5 MB
__device__ float g_scratch[1024 * 64 * 64];     // 16.8 MB

// ---------------------------------------------------------------------------
// helpers
// ---------------------------------------------------------------------------
__device__ __forceinline__ uint32_t smem_u32(const void* p) {
    uint32_t a;
    asm("{ .reg .u64 t; cvta.to.shared.u64 t, %1; cvt.u32.u64 %0, t; }" : "=r"(a) : "l"(p));
    return a;
}
__device__ __forceinline__ uint32_t f2tf32(float f) {
    uint32_t r;
    asm("cvt.rna.tf32.f32 %0, %1;" : "=r"(r) : "f"(f));
    return r;
}
#define SWZ(o) ((o) ^ (((o) >> 3) & 0x70))

#if HAS_TCGEN05
__device__ __forceinline__ uint32_t elect_one() {
    uint32_t p;
    asm volatile("{ .reg .pred p; elect.sync _|p, 0xFFFFFFFF; selp.b32 %0,1,0,p; }" : "=r"(p));
    return p;
}

// K-major SW128: LBO=1, SBO=64 (proven rounds 4-6)
static constexpr uint64_t DESC_BASE =
    (uint64_t(2) << 61) | (uint64_t(1) << 46) | (uint64_t(64) << 32) | (uint64_t(1) << 16);
__device__ __forceinline__ uint64_t make_desc(uint32_t addr) {
    return DESC_BASE | ((uint64_t)(addr >> 4) & 0x3FFF);
}

// idesc kind::tf32: dtype=F32(1)<<4, atype=TF32(2)<<7, btype=TF32(2)<<10,
// N=64 -> 8<<17, M=128 -> 8<<24   (proven rounds 4-6)
#define IDESC_TF32 0x8100910u

__device__ __forceinline__ void mma_tf32(uint32_t d, uint64_t ad, uint64_t bd, uint32_t en) {
    asm volatile(
        "{\n\t.reg .pred p;\n\tsetp.ne.u32 p, %4, 0;\n\t"
        "tcgen05.mma.cta_group::1.kind::tf32 [%0], %1, %2, %3, {%5,%5,%5,%5}, p;\n\t}"
        :: "r"(d), "l"(ad), "l"(bd), "r"(IDESC_TF32), "r"(en), "r"(0u) : "memory");
}

#define MBARRIER_INIT(a, c) \
    asm volatile("mbarrier.init.shared.b64 [%0], %1;" :: "r"(a), "r"(c) : "memory")

#define MBAR_WAIT(addr, ph) do { \
    uint32_t _a = (addr), _p = (ph) & 1, _d; \
    asm volatile("{\n\t.reg .pred p;\n\tmbarrier.try_wait.parity.acquire.cta.shared::cta.b64 p, [%1], %2;\n\tselp.b32 %0,1,0,p;\n\t}" \
        : "=r"(_d) : "r"(_a), "r"(_p) : "memory"); \
    while (!_d) { \
        asm volatile("{\n\t.reg .pred p;\n\tmbarrier.try_wait.parity.acquire.cta.shared::cta.b64 p, [%1], %2, 0x989680;\n\tselp.b32 %0,1,0,p;\n\t}" \
            : "=r"(_d) : "r"(_a), "r"(_p) : "memory"); \
    } \
} while (0)

#define TCG_COMMIT(mb) \
    asm volatile("tcgen05.commit.cta_group::1.mbarrier::arrive::one.shared::cluster.b64 [%0];" :: "r"(mb) : "memory")
#define TCG_ALLOC(sa, n) \
    asm volatile("tcgen05.alloc.cta_group::1.sync.aligned.shared::cta.b32 [%0], %1;" :: "r"(sa), "r"(n) : "memory")
#define TCG_DEALLOC(t, n) \
    asm volatile("tcgen05.dealloc.cta_group::1.sync.aligned.b32 %0, %1;" :: "r"(t), "r"(n))
#define TCG_RELINQ() \
    asm volatile("tcgen05.relinquish_alloc_permit.cta_group::1.sync.aligned;")
#define TCG_WAIT_LD() asm volatile("tcgen05.wait::ld.sync.aligned;" ::: "memory")
#define TCG_FENCE_AFTER() asm volatile("tcgen05.fence::after_thread_sync;" ::: "memory")

#define TCG_LD_X32(r, ta) \
    asm volatile("tcgen05.ld.sync.aligned.32x32b.x32.b32 " \
        "{%0,%1,%2,%3,%4,%5,%6,%7,%8,%9,%10,%11,%12,%13,%14,%15," \
        "%16,%17,%18,%19,%20,%21,%22,%23,%24,%25,%26,%27,%28,%29,%30,%31}, [%32];" \
        : "=r"((r)[0]), "=r"((r)[1]), "=r"((r)[2]), "=r"((r)[3]), \
          "=r"((r)[4]), "=r"((r)[5]), "=r"((r)[6]), "=r"((r)[7]), \
          "=r"((r)[8]), "=r"((r)[9]), "=r"((r)[10]), "=r"((r)[11]), \
          "=r"((r)[12]), "=r"((r)[13]), "=r"((r)[14]), "=r"((r)[15]), \
          "=r"((r)[16]), "=r"((r)[17]), "=r"((r)[18]), "=r"((r)[19]), \
          "=r"((r)[20]), "=r"((r)[21]), "=r"((r)[22]), "=r"((r)[23]), \
          "=r"((r)[24]), "=r"((r)[25]), "=r"((r)[26]), "=r"((r)[27]), \
          "=r"((r)[28]), "=r"((r)[29]), "=r"((r)[30]), "=r"((r)[31]) \
        : "r"(ta))
#endif  // HAS_TCGEN05

// ---------------------------------------------------------------------------
// Pass 1: X (B=64, C=128, H=32, W=32) -> Xt (H, W, B, C)
// One block per (b, y): smem plane (c=128, x=32).
// ---------------------------------------------------------------------------
__global__ void __launch_bounds__(256) transpose_kernel(const float* __restrict__ X) {
    __shared__ float sm[128][33];
    const int bx = blockIdx.x;
    const int b  = bx >> 5;    // 0..63
    const int yy = bx & 31;    // 0..31
    const int t  = threadIdx.x;

    // Read coalesced along x: 8 c-rows per iter, 16 iters.
    #pragma unroll
    for (int p = 0; p < 16; p++) {
        const int c = p * 8 + (t >> 5);
        const int x = t & 31;
        sm[c][x] = X[(((b * 128 + c) * 32 + yy) << 5) + x];
    }
    __syncthreads();

    // Write coalesced along c: 2 x-columns per iter (2 x 512B), 16 iters.
    #pragma unroll
    for (int q = 0; q < 16; q++) {
        const int x = q * 2 + (t >> 7);
        const int c = t & 127;
        g_Xt[((((yy << 5) + x) << 6) + b) * 128 + c] = sm[c][x];
    }
}

// ---------------------------------------------------------------------------
// Pass 2: per-location GEMM (round-5 proven 2-stage structure, tap-major K)
// smem (bytes): A0 [0,8K) A1 [8K,16K) B0 [16K,24K) B1 [24K,32K);
//               mbar at 32768 (2 x u64); tmem ptr at 32784.
// A desc covers 128 rows; rows 64-127 alias the next region (garbage; D rows
// 64-127 never read).
// ---------------------------------------------------------------------------
__global__ void __launch_bounds__(256, 4) varconv_kernel(
    const float* __restrict__ W, const float* __restrict__ bias)
{
    const int s = blockIdx.x;
    const int y = s >> 5, x0 = s & 31;
    const int tid = threadIdx.x;
    const float bs = bias[s];

#if HAS_TCGEN05
    __shared__ __align__(1024) uint32_t sm[8200];
    const uint32_t smb = smem_u32(sm);
    char* smc = (char*)sm;

    const int wid = tid >> 5, lid = tid & 31;
    const int bq = tid & 63;        // batch row (A) / C_out row (B)
    const int kg = tid >> 6;        // k-subgroup 0..3 (8 k each)

    if (wid == 0) { TCG_ALLOC(smb + 32784, 64); TCG_RELINQ(); }
    if (tid == 0) { MBARRIER_INIT(smb + 32768, 1); MBARRIER_INIT(smb + 32768 + 8, 1); }
    __syncthreads();
    uint32_t tmem;
    asm("ld.shared.b32 %0, [%1];" : "=r"(tmem) : "r"(smb + 32784));

    const float* Wp = W + (size_t)s * 73728 + bq;   // + co
    const uint32_t bias_tf = f2tf32(bs);
    uint32_t av[8], bv[8];

    // chunk ci = tap*4 + q; covers original k = (q*32 + j)*9 + tap, j=0..31.
    auto loadAB = [&](int ci) {
        const int tap = ci >> 2;
        const int q   = ci & 3;
        const int yy  = y  + tap / 3 - 1;
        const int xx  = x0 + tap % 3 - 1;
        const int kb  = q * 32 + kg * 8;        // c-base for this thread
        if (((unsigned)yy < 32u) && ((unsigned)xx < 32u)) {
            const float4* ap = (const float4*)(g_Xt + ((((yy << 5) + xx) << 6) + bq) * 128 + kb);
            const float4 a0 = ap[0];
            const float4 a1 = ap[1];
            av[0] = f2tf32(a0.x + bs); av[1] = f2tf32(a0.y + bs);
            av[2] = f2tf32(a0.z + bs); av[3] = f2tf32(a0.w + bs);
            av[4] = f2tf32(a1.x + bs); av[5] = f2tf32(a1.y + bs);
            av[6] = f2tf32(a1.z + bs); av[7] = f2tf32(a1.w + bs);
        } else {
            #pragma unroll
            for (int u = 0; u < 8; u++) av[u] = bias_tf;
        }
        const float* wq = Wp + (size_t)(kb * 9 + tap) * 64;
        #pragma unroll
        for (int u = 0; u < 8; u++)
            bv[u] = f2tf32(__ldg(wq + u * 576));   // +9 rows of 64 per c step
    };

    loadAB(0);
    int ph0 = 0, ph1 = 0;
    const uint32_t off = (uint32_t)bq * 128 + (uint32_t)kg * 32;
    const uint32_t sw0 = SWZ(off), sw1 = SWZ(off + 16);

#define CHUNK(I, ST, PH) { \
    if ((I) >= 2) { MBAR_WAIT(smb + 32768 + (ST) * 8, PH); PH ^= 1; } \
    *(uint4*)(smc + (ST) * 8192 + sw0)         = make_uint4(av[0], av[1], av[2], av[3]); \
    *(uint4*)(smc + (ST) * 8192 + sw1)         = make_uint4(av[4], av[5], av[6], av[7]); \
    *(uint4*)(smc + 16384 + (ST) * 8192 + sw0) = make_uint4(bv[0], bv[1], bv[2], bv[3]); \
    *(uint4*)(smc + 16384 + (ST) * 8192 + sw1) = make_uint4(bv[4], bv[5], bv[6], bv[7]); \
    if ((I) + 1 < 36) loadAB((I) + 1); \
    asm volatile("fence.proxy.async.shared::cta;" ::: "memory"); \
    __syncthreads(); \
    if (wid == 0 && elect_one()) { \
        uint64_t ad = make_desc(smb + (ST) * 8192); \
        uint64_t bd = make_desc(smb + 16384 + (ST) * 8192); \
        mma_tf32(tmem, ad,     bd,     (I) > 0 ? 1u : 0u); \
        mma_tf32(tmem, ad + 2, bd + 2, 1u); \
        mma_tf32(tmem, ad + 4, bd + 4, 1u); \
        mma_tf32(tmem, ad + 6, bd + 6, 1u); \
        TCG_COMMIT(smb + 32768 + (ST) * 8); \
    } }

    for (int i = 0; i < 36; i += 2) {
        CHUNK(i, 0, ph0);
        CHUNK(i + 1, 1, ph1);
    }
#undef CHUNK

    MBAR_WAIT(smb + 32768, ph0);
    MBAR_WAIT(smb + 32768 + 8, ph1);
    TCG_FENCE_AFTER();

    if (wid < 2) {
        const int b = wid * 32 + lid;
        float* dst = g_scratch + ((size_t)s * 64 + b) * 64;
        uint32_t dr[32];
        TCG_LD_X32(dr, tmem);
        TCG_WAIT_LD();
        #pragma unroll
        for (int j = 0; j < 8; j++)
            ((uint4*)dst)[j] = make_uint4(dr[4 * j], dr[4 * j + 1], dr[4 * j + 2], dr[4 * j + 3]);
        TCG_LD_X32(dr, tmem + 32);
        TCG_WAIT_LD();
        #pragma unroll
        for (int j = 0; j < 8; j++)
            ((uint4*)(dst + 32))[j] = make_uint4(dr[4 * j], dr[4 * j + 1], dr[4 * j + 2], dr[4 * j + 3]);
    }
    __syncthreads();
    if (wid == 0) TCG_DEALLOC(tmem, 64);

#else  // ------- SIMT fallback (plain compute_103 pass; not selected on GB300)
    __shared__ float As[32][68];
    __shared__ float Bs[32][64];
    const int tx = tid & 15;
    const int ty = tid >> 4;
    const float* Wp = W + (size_t)s * 73728;

    float acc[4][4];
    #pragma unroll
    for (int i = 0; i < 4; i++)
        #pragma unroll
        for (int j = 0; j < 4; j++) acc[i][j] = 0.0f;

    for (int k0 = 0; k0 < 1152; k0 += 32) {
        {
            const float4* src = (const float4*)(Wp + k0 * 64);
            float4* dstB = (float4*)(&Bs[0][0]);
            dstB[tid]       = src[tid];
            dstB[tid + 256] = src[tid + 256];
        }
        #pragma unroll
        for (int i = 0; i < 2; i++) {
            const int kk = i * 16 + (tid >> 4);
            const int k  = k0 + kk;
            const int c   = k / 9;
            const int tap = k - c * 9;
            const int r   = tap / 3;
            const int cc  = tap - r * 3;
            const int yy = y + r - 1;
            const int xx = x0 + cc - 1;
            const int b4 = (tid & 15) << 2;
            float4 v = make_float4(0.f, 0.f, 0.f, 0.f);
            if (((unsigned)yy < 32u) && ((unsigned)xx < 32u)) {
                // Xt layout (y, x, b, c)
                v.x = g_Xt[((((yy << 5) + xx) << 6) + b4 + 0) * 128 + c];
                v.y = g_Xt[((((yy << 5) + xx) << 6) + b4 + 1) * 128 + c];
                v.z = g_Xt[((((yy << 5) + xx) << 6) + b4 + 2) * 128 + c];
                v.w = g_Xt[((((yy << 5) + xx) << 6) + b4 + 3) * 128 + c];
            }
            v.x += bs; v.y += bs; v.z += bs; v.w += bs;
            *(float4*)&As[kk][b4] = v;
        }
        __syncthreads();
        #pragma unroll
        for (int kk = 0; kk < 32; kk++) {
            const float4 a = *(const float4*)&As[kk][ty << 2];
            const float4 b = *(const float4*)&Bs[kk][tx << 2];
            acc[0][0] += a.x * b.x; acc[0][1] += a.x * b.y; acc[0][2] += a.x * b.z; acc[0][3] += a.x * b.w;
            acc[1][0] += a.y * b.x; acc[1][1] += a.y * b.y; acc[1][2] += a.y * b.z; acc[1][3] += a.y * b.w;
            acc[2][0] += a.z * b.x; acc[2][1] += a.z * b.y; acc[2][2] += a.z * b.z; acc[2][3] += a.z * b.w;
            acc[3][0] += a.w * b.x; acc[3][1] += a.w * b.y; acc[3][2] += a.w * b.z; acc[3][3] += a.w * b.w;
        }
        __syncthreads();
    }
    #pragma unroll
    for (int i = 0; i < 4; i++) {
        const int b = (ty << 2) + i;
        #pragma unroll
        for (int j = 0; j < 4; j++) {
            const int co = (tx << 2) + j;
            g_scratch[((size_t)s * 64 + b) * 64 + co] = acc[i][j];
        }
    }
#endif
}

// ---------------------------------------------------------------------------
// Pass 3: scratch (s, f) -> out (f, s), f = b*64 + co
// ---------------------------------------------------------------------------
__global__ void __launch_bounds__(256) out_transpose(float* __restrict__ out) {
    __shared__ float tile[32][33];
    const int f0 = blockIdx.x * 32;
    const int s0 = blockIdx.y * 32;
    const int tc = threadIdx.x & 31;
    const int tr = threadIdx.x >> 5;
    #pragma unroll
    for (int r = 0; r < 4; r++) {
        const int sl = tr * 4 + r;
        tile[sl][tc] = g_scratch[(size_t)(s0 + sl) * 4096 + f0 + tc];
    }
    __syncthreads();
    #pragma unroll
    for (int r = 0; r < 4; r++) {
        const int fl = tr * 4 + r;
        out[(size_t)(f0 + fl) * 1024 + s0 + tc] = tile[tc][fl];
    }
}

extern "C" void kernel_launch(void* const* d_in, const int* in_sizes, int n_in,
                              void* d_out, int out_size) {
    const float* X    = (const float*)d_in[0];
    const float* W    = (const float*)d_in[1];
    const float* bias = (const float*)d_in[2];
    float* out = (float*)d_out;

    transpose_kernel<<<64 * 32, 256>>>(X);
    varconv_kernel<<<1024, 256>>>(W, bias);
    out_transpose<<<dim3(128, 32), 256>>>(out);
}

// round 12
// speedup vs baseline: 1.6346x; 1.3651x over previous
#include <cuda_runtime.h>
#include <cstdint>

// VarConvND via tcgen05 TF32 per-location GEMM (sm_103a), SIMT fallback body
// for the plain compute_103 PTX pass (never selected at runtime on GB300).
//
//   out[b, co, s] = sum_k (unfold(X)[b, k, s] + bias[s]) * weight[s, k, co]
// Decomposed: out = unfold(X)^T W + bias[s] * colsum_k(W[s,:,co]).
//
// ROLE SWAP: A-operand = W[co][k] (M=co pad 128), B-operand = act[b][k] (N=64).
// K permuted tap-major (k' = tap*128 + c): activation chunk = contiguous 8KB
// block of Xt(y,x,b,c), filled with 2xLDG.128/thread (8 lanes per b-row,
// nL=4/inst). W chunk filled with the proven transposing 8xLDG.32.
//
// Pass 1: X (B,C,H,W) -> Xt (H,W,B,C), tf32-rounded (rna).
// Pass 2: one block per s, 2-stage pipeline (proven round-5 skeleton).
//         D[co][b] -> scratch[s][co][b] (coalesced).
// Pass 3: scratch (s, co, b) -> out (b*64+co, s).

#if defined(__CUDA_ARCH_FEAT_SM103_ALL) || defined(__CUDA_ARCH_FEAT_SM100_ALL)
#define HAS_TCGEN05 1
#else
#define HAS_TCGEN05 0
#endif

__device__ float g_Xt[32 * 32 * 64 * 128];      // (y, x, b, c) 33.5 MB
__device__ float g_scratch[1024 * 64 * 64];     // (s, co, b)   16.8 MB

// ---------------------------------------------------------------------------
// helpers
// ---------------------------------------------------------------------------
__device__ __forceinline__ uint32_t smem_u32(const void* p) {
    uint32_t a;
    asm("{ .reg .u64 t; cvta.to.shared.u64 t, %1; cvt.u32.u64 %0, t; }" : "=r"(a) : "l"(p));
    return a;
}
__device__ __forceinline__ uint32_t f2tf32(float f) {
    uint32_t r;
    asm("cvt.rna.tf32.f32 %0, %1;" : "=r"(r) : "f"(f));
    return r;
}
#define SWZ(o) ((o) ^ (((o) >> 3) & 0x70))

#if HAS_TCGEN05
__device__ __forceinline__ uint32_t elect_one() {
    uint32_t p;
    asm volatile("{ .reg .pred p; elect.sync _|p, 0xFFFFFFFF; selp.b32 %0,1,0,p; }" : "=r"(p));
    return p;
}

// K-major SW128: LBO=1, SBO=64 (proven rounds 4-6)
static constexpr uint64_t DESC_BASE =
    (uint64_t(2) << 61) | (uint64_t(1) << 46) | (uint64_t(64) << 32) | (uint64_t(1) << 16);
__device__ __forceinline__ uint64_t make_desc(uint32_t addr) {
    return DESC_BASE | ((uint64_t)(addr >> 4) & 0x3FFF);
}

// idesc kind::tf32: dtype=F32(1)<<4, atype=TF32(2)<<7, btype=TF32(2)<<10,
// N=64 -> 8<<17, M=128 -> 8<<24   (proven rounds 4-6)
#define IDESC_TF32 0x8100910u

__device__ __forceinline__ void mma_tf32(uint32_t d, uint64_t ad, uint64_t bd, uint32_t en) {
    asm volatile(
        "{\n\t.reg .pred p;\n\tsetp.ne.u32 p, %4, 0;\n\t"
        "tcgen05.mma.cta_group::1.kind::tf32 [%0], %1, %2, %3, {%5,%5,%5,%5}, p;\n\t}"
        :: "r"(d), "l"(ad), "l"(bd), "r"(IDESC_TF32), "r"(en), "r"(0u) : "memory");
}

#define MBARRIER_INIT(a, c) \
    asm volatile("mbarrier.init.shared.b64 [%0], %1;" :: "r"(a), "r"(c) : "memory")

#define MBAR_WAIT(addr, ph) do { \
    uint32_t _a = (addr), _p = (ph) & 1, _d; \
    asm volatile("{\n\t.reg .pred p;\n\tmbarrier.try_wait.parity.acquire.cta.shared::cta.b64 p, [%1], %2;\n\tselp.b32 %0,1,0,p;\n\t}" \
        : "=r"(_d) : "r"(_a), "r"(_p) : "memory"); \
    while (!_d) { \
        asm volatile("{\n\t.reg .pred p;\n\tmbarrier.try_wait.parity.acquire.cta.shared::cta.b64 p, [%1], %2, 0x989680;\n\tselp.b32 %0,1,0,p;\n\t}" \
            : "=r"(_d) : "r"(_a), "r"(_p) : "memory"); \
    } \
} while (0)

#define TCG_COMMIT(mb) \
    asm volatile("tcgen05.commit.cta_group::1.mbarrier::arrive::one.shared::cluster.b64 [%0];" :: "r"(mb) : "memory")
#define TCG_ALLOC(sa, n) \
    asm volatile("tcgen05.alloc.cta_group::1.sync.aligned.shared::cta.b32 [%0], %1;" :: "r"(sa), "r"(n) : "memory")
#define TCG_DEALLOC(t, n) \
    asm volatile("tcgen05.dealloc.cta_group::1.sync.aligned.b32 %0, %1;" :: "r"(t), "r"(n))
#define TCG_RELINQ() \
    asm volatile("tcgen05.relinquish_alloc_permit.cta_group::1.sync.aligned;")
#define TCG_WAIT_LD() asm volatile("tcgen05.wait::ld.sync.aligned;" ::: "memory")
#define TCG_FENCE_AFTER() asm volatile("tcgen05.fence::after_thread_sync;" ::: "memory")

#define TCG_LD_X32(r, ta) \
    asm volatile("tcgen05.ld.sync.aligned.32x32b.x32.b32 " \
        "{%0,%1,%2,%3,%4,%5,%6,%7,%8,%9,%10,%11,%12,%13,%14,%15," \
        "%16,%17,%18,%19,%20,%21,%22,%23,%24,%25,%26,%27,%28,%29,%30,%31}, [%32];" \
        : "=r"((r)[0]), "=r"((r)[1]), "=r"((r)[2]), "=r"((r)[3]), \
          "=r"((r)[4]), "=r"((r)[5]), "=r"((r)[6]), "=r"((r)[7]), \
          "=r"((r)[8]), "=r"((r)[9]), "=r"((r)[10]), "=r"((r)[11]), \
          "=r"((r)[12]), "=r"((r)[13]), "=r"((r)[14]), "=r"((r)[15]), \
          "=r"((r)[16]), "=r"((r)[17]), "=r"((r)[18]), "=r"((r)[19]), \
          "=r"((r)[20]), "=r"((r)[21]), "=r"((r)[22]), "=r"((r)[23]), \
          "=r"((r)[24]), "=r"((r)[25]), "=r"((r)[26]), "=r"((r)[27]), \
          "=r"((r)[28]), "=r"((r)[29]), "=r"((r)[30]), "=r"((r)[31]) \
        : "r"(ta))
#endif  // HAS_TCGEN05

// ---------------------------------------------------------------------------
// Pass 1: X (B=64, C=128, H=32, W=32) -> Xt (H, W, B, C), tf32-rounded.
// One block per (b, y): smem plane (c=128, x=32).
// ---------------------------------------------------------------------------
__global__ void __launch_bounds__(256) transpose_kernel(const float* __restrict__ X) {
    __shared__ float sm[128][33];
    const int bx = blockIdx.x;
    const int b  = bx >> 5;    // 0..63
    const int yy = bx & 31;    // 0..31
    const int t  = threadIdx.x;

    #pragma unroll
    for (int p = 0; p < 16; p++) {
        const int c = p * 8 + (t >> 5);
        const int x = t & 31;
        sm[c][x] = X[(((b * 128 + c) * 32 + yy) << 5) + x];
    }
    __syncthreads();
    #pragma unroll
    for (int q = 0; q < 16; q++) {
        const int x = q * 2 + (t >> 7);
        const int c = t & 127;
        g_Xt[((((yy << 5) + x) << 6) + b) * 128 + c] = __uint_as_float(f2tf32(sm[c][x]));
    }
}

// ---------------------------------------------------------------------------
// Pass 2: per-location GEMM (role-swapped, tap-major K, 2-stage pipeline)
// smem (bytes): W(A) stages [0,16K); Act(B) stages [16K,32K);
//   mbar 32768 (2 x u64); tmem ptr 32784; cs4 [32800,33824); cs [33824,34080)
// ---------------------------------------------------------------------------
__global__ void __launch_bounds__(256, 4) varconv_kernel(
    const float* __restrict__ W, const float* __restrict__ bias)
{
    const int s = blockIdx.x;
    const int y = s >> 5, x0 = s & 31;
    const int tid = threadIdx.x;
    const float bs = bias[s];

#if HAS_TCGEN05
    __shared__ __align__(1024) uint32_t sm[8520];
    const uint32_t smb = smem_u32(sm);
    char* smc = (char*)sm;

    const int wid = tid >> 5, lid = tid & 31;
    const int bq = tid & 63;        // co row (W / A-operand)
    const int kg = tid >> 6;        // k-subgroup 0..3 (8 k each)

    if (wid == 0) { TCG_ALLOC(smb + 32784, 64); TCG_RELINQ(); }
    if (tid == 0) { MBARRIER_INIT(smb + 32768, 1); MBARRIER_INIT(smb + 32768 + 8, 1); }
    __syncthreads();
    uint32_t tmem;
    asm("ld.shared.b32 %0, [%1];" : "=r"(tmem) : "r"(smb + 32784));

    const float* Wp = W + (size_t)s * 73728 + bq;   // + co
    float csum = 0.0f;
    uint32_t wv[8];
    uint4 act0, act1;

    // Act fill mapping: granules g0 = tid, g1 = tid + 256 of 512 (64 b-rows x
    // 8 x 16B). row = g>>3, gj = g&7. Lanes 0-7 share a row -> nL=4 per LDG.128.
    const int r0 = tid >> 3, gj = tid & 7;

    // chunk ci = tap*4 + q covers original k = (q*32 + j)*9 + tap, j=0..31.
    auto loadAB = [&](int ci) {
        const int tap = ci >> 2;
        const int q   = ci & 3;
        const int yy  = y  + tap / 3 - 1;
        const int xx  = x0 + tap % 3 - 1;
        const int kb  = q * 32 + kg * 8;        // c-base for W rows
        // W (A-role): 8 coalesced LDG.32, stride 576 floats; cvt + colsum.
        const float* wq = Wp + (size_t)(kb * 9 + tap) * 64;
        #pragma unroll
        for (int u = 0; u < 8; u++) {
            wv[u] = f2tf32(__ldg(wq + u * 576));
            csum += __uint_as_float(wv[u]);
        }
        // Act (B-role): 2 x LDG.128 from contiguous 8KB Xt block (or zeros).
        if (((unsigned)yy < 32u) && ((unsigned)xx < 32u)) {
            const float* base = g_Xt + (size_t)((((yy << 5) + xx) << 6)) * 128 + q * 32 + gj * 4;
            act0 = *(const uint4*)(base + (size_t)r0 * 128);
            act1 = *(const uint4*)(base + (size_t)(r0 + 32) * 128);
        } else {
            act0 = make_uint4(0, 0, 0, 0);
            act1 = make_uint4(0, 0, 0, 0);
        }
    };

    loadAB(0);
    int ph0 = 0, ph1 = 0;
    const uint32_t woff = (uint32_t)bq * 128 + (uint32_t)kg * 32;
    const uint32_t wsw0 = SWZ(woff), wsw1 = SWZ(woff + 16);
    const uint32_t asw0 = SWZ((uint32_t)r0 * 128 + (uint32_t)gj * 16);
    const uint32_t asw1 = SWZ((uint32_t)(r0 + 32) * 128 + (uint32_t)gj * 16);

#define CHUNK(I, ST, PH) { \
    if ((I) >= 2) { MBAR_WAIT(smb + 32768 + (ST) * 8, PH); PH ^= 1; } \
    *(uint4*)(smc + (ST) * 8192 + wsw0)         = make_uint4(wv[0], wv[1], wv[2], wv[3]); \
    *(uint4*)(smc + (ST) * 8192 + wsw1)         = make_uint4(wv[4], wv[5], wv[6], wv[7]); \
    *(uint4*)(smc + 16384 + (ST) * 8192 + asw0) = act0; \
    *(uint4*)(smc + 16384 + (ST) * 8192 + asw1) = act1; \
    if ((I) + 1 < 36) loadAB((I) + 1); \
    asm volatile("fence.proxy.async.shared::cta;" ::: "memory"); \
    __syncthreads(); \
    if (wid == 0 && elect_one()) { \
        uint64_t ad = make_desc(smb + (ST) * 8192); \
        uint64_t bd = make_desc(smb + 16384 + (ST) * 8192); \
        mma_tf32(tmem, ad,     bd,     (I) > 0 ? 1u : 0u); \
        mma_tf32(tmem, ad + 2, bd + 2, 1u); \
        mma_tf32(tmem, ad + 4, bd + 4, 1u); \
        mma_tf32(tmem, ad + 6, bd + 6, 1u); \
        TCG_COMMIT(smb + 32768 + (ST) * 8); \
    } }

    for (int i = 0; i < 36; i += 2) {
        CHUNK(i, 0, ph0);
        CHUNK(i + 1, 1, ph1);
    }
#undef CHUNK

    // colsum reduction: cs[co] = sum over 4 kg partials
    ((float*)(smc + 32800))[kg * 64 + bq] = csum;
    __syncthreads();
    if (tid < 64) {
        const float* c4 = (const float*)(smc + 32800);
        ((float*)(smc + 33824))[tid] = c4[tid] + c4[64 + tid] + c4[128 + tid] + c4[192 + tid];
    }
    __syncthreads();

    MBAR_WAIT(smb + 32768, ph0);
    MBAR_WAIT(smb + 32768 + 8, ph1);
    TCG_FENCE_AFTER();

    // D[co][b]: warps 0,1 read rows co=0..63, add bias*colsum[co], write
    // scratch[s][co][b] coalesced (256B per thread).
    if (wid < 2) {
        const int co = wid * 32 + lid;
        const float corr = bs * ((const float*)(smc + 33824))[co];
        float* dst = g_scratch + ((size_t)s * 64 + co) * 64;
        uint32_t dr[32];
        TCG_LD_X32(dr, tmem);
        TCG_WAIT_LD();
        #pragma unroll
        for (int c = 0; c < 32; c++)
            dr[c] = __float_as_uint(__uint_as_float(dr[c]) + corr);
        #pragma unroll
        for (int j = 0; j < 8; j++)
            ((uint4*)dst)[j] = make_uint4(dr[4 * j], dr[4 * j + 1], dr[4 * j + 2], dr[4 * j + 3]);
        TCG_LD_X32(dr, tmem + 32);
        TCG_WAIT_LD();
        #pragma unroll
        for (int c = 0; c < 32; c++)
            dr[c] = __float_as_uint(__uint_as_float(dr[c]) + corr);
        #pragma unroll
        for (int j = 0; j < 8; j++)
            ((uint4*)(dst + 32))[j] = make_uint4(dr[4 * j], dr[4 * j + 1], dr[4 * j + 2], dr[4 * j + 3]);
    }
    __syncthreads();
    if (wid == 0) TCG_DEALLOC(tmem, 64);

#else  // ------- SIMT fallback (plain compute_103 pass; not selected on GB300)
    __shared__ float As[32][68];
    __shared__ float Bs[32][64];
    const int tx = tid & 15;
    const int ty = tid >> 4;
    const float* Wp = W + (size_t)s * 73728;

    float acc[4][4];
    #pragma unroll
    for (int i = 0; i < 4; i++)
        #pragma unroll
        for (int j = 0; j < 4; j++) acc[i][j] = 0.0f;

    for (int k0 = 0; k0 < 1152; k0 += 32) {
        {
            const float4* src = (const float4*)(Wp + k0 * 64);
            float4* dstB = (float4*)(&Bs[0][0]);
            dstB[tid]       = src[tid];
            dstB[tid + 256] = src[tid + 256];
        }
        #pragma unroll
        for (int i = 0; i < 2; i++) {
            const int kk = i * 16 + (tid >> 4);
            const int k  = k0 + kk;
            const int c   = k / 9;
            const int tap = k - c * 9;
            const int r   = tap / 3;
            const int cc  = tap - r * 3;
            const int yy = y + r - 1;
            const int xx = x0 + cc - 1;
            const int b4 = (tid & 15) << 2;
            float4 v = make_float4(0.f, 0.f, 0.f, 0.f);
            if (((unsigned)yy < 32u) && ((unsigned)xx < 32u)) {
                v.x = g_Xt[((((yy << 5) + xx) << 6) + b4 + 0) * 128 + c];
                v.y = g_Xt[((((yy << 5) + xx) << 6) + b4 + 1) * 128 + c];
                v.z = g_Xt[((((yy << 5) + xx) << 6) + b4 + 2) * 128 + c];
                v.w = g_Xt[((((yy << 5) + xx) << 6) + b4 + 3) * 128 + c];
            }
            v.x += bs; v.y += bs; v.z += bs; v.w += bs;
            *(float4*)&As[kk][b4] = v;
        }
        __syncthreads();
        #pragma unroll
        for (int kk = 0; kk < 32; kk++) {
            const float4 a = *(const float4*)&As[kk][ty << 2];
            const float4 b = *(const float4*)&Bs[kk][tx << 2];
            acc[0][0] += a.x * b.x; acc[0][1] += a.x * b.y; acc[0][2] += a.x * b.z; acc[0][3] += a.x * b.w;
            acc[1][0] += a.y * b.x; acc[1][1] += a.y * b.y; acc[1][2] += a.y * b.z; acc[1][3] += a.y * b.w;
            acc[2][0] += a.z * b.x; acc[2][1] += a.z * b.y; acc[2][2] += a.z * b.z; acc[2][3] += a.z * b.w;
            acc[3][0] += a.w * b.x; acc[3][1] += a.w * b.y; acc[3][2] += a.w * b.z; acc[3][3] += a.w * b.w;
        }
        __syncthreads();
    }
    #pragma unroll
    for (int i = 0; i < 4; i++) {
        const int b = (ty << 2) + i;
        #pragma unroll
        for (int j = 0; j < 4; j++) {
            const int co = (tx << 2) + j;
            g_scratch[((size_t)s * 64 + co) * 64 + b] = acc[i][j];
        }
    }
#endif
}

// ---------------------------------------------------------------------------
// Pass 3: scratch (s, co, b) -> out (b*64+co, s)
// Block: co = blockIdx.x, s-tile of 64 = blockIdx.y.
// ---------------------------------------------------------------------------
__global__ void __launch_bounds__(256) out_transpose(float* __restrict__ out) {
    __shared__ float tile[64][65];   // [s][b]
    const int co = blockIdx.x;
    const int s0 = blockIdx.y * 64;
    const int t  = threadIdx.x;

    #pragma unroll
    for (int r = 0; r < 4; r++) {
        const int gi = r * 256 + t;
        const int si = gi >> 4;
        const int gjj = gi & 15;
        const float4 v = *(const float4*)(g_scratch + (size_t)(s0 + si) * 4096 + co * 64 + gjj * 4);
        tile[si][gjj * 4 + 0] = v.x;
        tile[si][gjj * 4 + 1] = v.y;
        tile[si][gjj * 4 + 2] = v.z;
        tile[si][gjj * 4 + 3] = v.w;
    }
    __syncthreads();
    #pragma unroll
    for (int r = 0; r < 4; r++) {
        const int gi = r * 256 + t;
        const int b  = gi >> 4;
        const int sj = gi & 15;
        float4 v;
        v.x = tile[sj * 4 + 0][b];
        v.y = tile[sj * 4 + 1][b];
        v.z = tile[sj * 4 + 2][b];
        v.w = tile[sj * 4 + 3][b];
        *(float4*)(out + (size_t)(b * 64 + co) * 1024 + s0 + sj * 4) = v;
    }
}

extern "C" void kernel_launch(void* const* d_in, const int* in_sizes, int n_in,
                              void* d_out, int out_size) {
    const float* X    = (const float*)d_in[0];
    const float* W    = (const float*)d_in[1];
    const float* bias = (const float*)d_in[2];
    float* out = (float*)d_out;

    transpose_kernel<<<64 * 32, 256>>>(X);
    varconv_kernel<<<1024, 256>>>(W, bias);
    out_transpose<<<dim3(64, 16), 256>>>(out);
}